// round 2
// baseline (speedup 1.0000x reference)
#include <cuda_runtime.h>
#include <math.h>

// AttentionPairBias: B=1, S=1024, ca=1024, cs=512, cz=64, H=16, c=64
#define S    1024
#define CA   1024
#define CS   512
#define CZ   64
#define NH   16
#define HC   64
#define EPSV 1e-5f

// ---------------- scratch (static device allocations; no cudaMalloc) ----------------
__device__ float g_sn[S * CS];        // LN(s)*sn_w                     2 MB
__device__ float g_an[S * CA];        // LN(a)                          4 MB
__device__ float g_a1[S * CA];        // adaLN output                   4 MB
__device__ float g_Q[NH * S * HC];    // per-head q   [h][y][c]         4 MB
__device__ float g_K[NH * S * HC];    // per-head k   [h][x][c]         4 MB
__device__ float g_V[NH * S * HC];    // per-head v                     4 MB
__device__ float g_G[NH * S * HC];    // sigmoid(g)                     4 MB
__device__ float g_bias[(size_t)NH * S * S]; // bias -> scores -> A    64 MB
__device__ float g_GO[S * CA];        // (g*o) in flat [s][e] layout    4 MB

// ---------------- helpers ----------------
__device__ __forceinline__ float warp_sum(float v) {
#pragma unroll
    for (int o = 16; o; o >>= 1) v += __shfl_xor_sync(0xffffffffu, v, o);
    return v;
}
__device__ __forceinline__ float warp_max(float v) {
#pragma unroll
    for (int o = 16; o; o >>= 1) v = fmaxf(v, __shfl_xor_sync(0xffffffffu, v, o));
    return v;
}
__device__ __forceinline__ float sigm(float x) { return 1.f / (1.f + __expf(-x)); }

__device__ __forceinline__ void fma44(float (&acc)[4][4], float4 a, float4 b) {
    float ar[4] = {a.x, a.y, a.z, a.w};
    float br[4] = {b.x, b.y, b.z, b.w};
#pragma unroll
    for (int i = 0; i < 4; i++)
#pragma unroll
        for (int j = 0; j < 4; j++) acc[i][j] += ar[i] * br[j];
}

// transposed store of a K-slice into smem tile [16][68]
__device__ __forceinline__ void stsT(float (*Sm)[68], int lc, int lr, float4 v) {
    Sm[lc + 0][lr] = v.x; Sm[lc + 1][lr] = v.y;
    Sm[lc + 2][lr] = v.z; Sm[lc + 3][lr] = v.w;
}

// ---------------- 1. s_n = LN(s) * sn_w  (1024 rows x 512) ----------------
__global__ void ln_s_kernel(const float* __restrict__ s, const float* __restrict__ snw) {
    __shared__ float sm[16];
    int row = blockIdx.x, tid = threadIdx.x;
    const float* x = s + row * CS;
    float2 v = *(const float2*)(x + tid * 2);
    float su = v.x + v.y, sq = v.x * v.x + v.y * v.y;
    su = warp_sum(su); sq = warp_sum(sq);
    if ((tid & 31) == 0) { sm[tid >> 5] = su; sm[8 + (tid >> 5)] = sq; }
    __syncthreads();
    float ts = 0.f, tq = 0.f;
#pragma unroll
    for (int i = 0; i < 8; i++) { ts += sm[i]; tq += sm[8 + i]; }
    float m = ts * (1.f / CS);
    float rs = rsqrtf(tq * (1.f / CS) - m * m + EPSV);
    float2 w = *(const float2*)(snw + tid * 2);
    float2 r; r.x = (v.x - m) * rs * w.x; r.y = (v.y - m) * rs * w.y;
    *(float2*)(g_sn + row * CS + tid * 2) = r;
}

// ---------------- 2. a_n = LN(a)  (1024 rows x 1024, no affine) ----------------
__global__ void ln_a_kernel(const float* __restrict__ a) {
    __shared__ float sm[16];
    int row = blockIdx.x, tid = threadIdx.x;
    const float* x = a + row * CA;
    float4 v = *(const float4*)(x + tid * 4);
    float su = v.x + v.y + v.z + v.w;
    float sq = v.x * v.x + v.y * v.y + v.z * v.z + v.w * v.w;
    su = warp_sum(su); sq = warp_sum(sq);
    if ((tid & 31) == 0) { sm[tid >> 5] = su; sm[8 + (tid >> 5)] = sq; }
    __syncthreads();
    float ts = 0.f, tq = 0.f;
#pragma unroll
    for (int i = 0; i < 8; i++) { ts += sm[i]; tq += sm[8 + i]; }
    float m = ts * (1.f / CA);
    float rs = rsqrtf(tq * (1.f / CA) - m * m + EPSV);
    float4 r;
    r.x = (v.x - m) * rs; r.y = (v.y - m) * rs;
    r.z = (v.z - m) * rs; r.w = (v.w - m) * rs;
    *(float4*)(g_an + row * CA + tid * 4) = r;
}

// ---------------- 3. a1 = sigmoid((s_n@pb_w^T + pb_b) * a_n + s_n@pn_w^T) ----------------
// dual GEMM: M=1024, N=1024, K=512
__global__ void adaln_gemm_kernel(const float* __restrict__ pbw, const float* __restrict__ pbb,
                                  const float* __restrict__ pnw) {
    __shared__ float As[16][68], B1s[16][68], B2s[16][68];
    int tid = threadIdx.x;
    int m0 = blockIdx.y * 64, n0 = blockIdx.x * 64;
    int lr = tid >> 2, lc = (tid & 3) * 4;
    int ty = tid >> 4, tx = tid & 15;
    float acc1[4][4] = {}, acc2[4][4] = {};
    for (int kt = 0; kt < CS; kt += 16) {
        stsT(As,  lc, lr, *(const float4*)(g_sn + (m0 + lr) * CS + kt + lc));
        stsT(B1s, lc, lr, *(const float4*)(pbw  + (n0 + lr) * CS + kt + lc));
        stsT(B2s, lc, lr, *(const float4*)(pnw  + (n0 + lr) * CS + kt + lc));
        __syncthreads();
#pragma unroll
        for (int k = 0; k < 16; k++) {
            float4 av = *(const float4*)&As[k][ty * 4];
            fma44(acc1, av, *(const float4*)&B1s[k][tx * 4]);
            fma44(acc2, av, *(const float4*)&B2s[k][tx * 4]);
        }
        __syncthreads();
    }
    float4 bbv = *(const float4*)(pbb + n0 + tx * 4);
    float bb[4] = {bbv.x, bbv.y, bbv.z, bbv.w};
#pragma unroll
    for (int i = 0; i < 4; i++) {
        int row = m0 + ty * 4 + i;
        float4 anv = *(const float4*)(g_an + row * CA + n0 + tx * 4);
        float an[4] = {anv.x, anv.y, anv.z, anv.w};
        float4 r;
        r.x = sigm((acc1[i][0] + bb[0]) * an[0] + acc2[i][0]);
        r.y = sigm((acc1[i][1] + bb[1]) * an[1] + acc2[i][1]);
        r.z = sigm((acc1[i][2] + bb[2]) * an[2] + acc2[i][2]);
        r.w = sigm((acc1[i][3] + bb[3]) * an[3] + acc2[i][3]);
        *(float4*)(g_a1 + row * CA + n0 + tx * 4) = r;
    }
}

// ---------------- 4. Q = a1 @ q_w^T + q_b, scattered into [h][y][c] ----------------
__global__ void q_gemm_kernel(const float* __restrict__ qw, const float* __restrict__ qb) {
    __shared__ float As[16][68], Bs[16][68];
    int tid = threadIdx.x;
    int m0 = blockIdx.y * 64, n0 = blockIdx.x * 64;
    int lr = tid >> 2, lc = (tid & 3) * 4;
    int ty = tid >> 4, tx = tid & 15;
    float acc[4][4] = {};
    for (int kt = 0; kt < CA; kt += 16) {
        stsT(As, lc, lr, *(const float4*)(g_a1 + (m0 + lr) * CA + kt + lc));
        stsT(Bs, lc, lr, *(const float4*)(qw   + (n0 + lr) * CA + kt + lc));
        __syncthreads();
#pragma unroll
        for (int k = 0; k < 16; k++)
            fma44(acc, *(const float4*)&As[k][ty * 4], *(const float4*)&Bs[k][tx * 4]);
        __syncthreads();
    }
    float4 qbv = *(const float4*)(qb + n0 + tx * 4);
    float qbb[4] = {qbv.x, qbv.y, qbv.z, qbv.w};
#pragma unroll
    for (int i = 0; i < 4; i++) {
        int row = m0 + ty * 4 + i;
        int col0 = n0 + tx * 4;
        int h = row >> 6;
        int y = ((row & 63) << 4) + (col0 >> 6);
        int cc = col0 & 63;
        float4 r = {acc[i][0] + qbb[0], acc[i][1] + qbb[1],
                    acc[i][2] + qbb[2], acc[i][3] + qbb[3]};
        *(float4*)(g_Q + (h << 16) + y * 64 + cc) = r;
    }
}

// ---------------- 5. KVG = a1 @ kvg_w^T, scattered into K/V/sigmoid(G) ----------------
__global__ void kvg_gemm_kernel(const float* __restrict__ kvgw) {
    __shared__ float As[16][68], Bs[16][68];
    int tid = threadIdx.x;
    int m0 = blockIdx.y * 64, n0 = blockIdx.x * 64;  // n over 3072
    int lr = tid >> 2, lc = (tid & 3) * 4;
    int ty = tid >> 4, tx = tid & 15;
    float acc[4][4] = {};
    for (int kt = 0; kt < CA; kt += 16) {
        stsT(As, lc, lr, *(const float4*)(g_a1 + (m0 + lr) * CA + kt + lc));
        stsT(Bs, lc, lr, *(const float4*)(kvgw + (n0 + lr) * CA + kt + lc));
        __syncthreads();
#pragma unroll
        for (int k = 0; k < 16; k++)
            fma44(acc, *(const float4*)&As[k][ty * 4], *(const float4*)&Bs[k][tx * 4]);
        __syncthreads();
    }
#pragma unroll
    for (int i = 0; i < 4; i++) {
        int row = m0 + ty * 4 + i;
        int col0 = n0 + tx * 4;          // group of 4 never crosses a 64/192 boundary
        int h = row >> 6;
        int y = ((row & 63) << 4) + col0 / 192;
        int t0 = col0 % 192;
        int which = t0 >> 6;
        int cc = t0 & 63;
        float4 r = {acc[i][0], acc[i][1], acc[i][2], acc[i][3]};
        int off = (h << 16) + y * 64 + cc;
        if (which == 0) {
            *(float4*)(g_K + off) = r;
        } else if (which == 1) {
            *(float4*)(g_V + off) = r;
        } else {
            float4 rg = {sigm(r.x), sigm(r.y), sigm(r.z), sigm(r.w)};
            *(float4*)(g_G + off) = rg;
        }
    }
}

// ---------------- 6. bias[h][x][y] from z (LN + 16x64 matvec), permuted layout ----------------
// one block per bias row (h,x): reads 64 consecutive z vectors (4096 contiguous floats)
__global__ void bias_z_kernel(const float* __restrict__ z,
                              const float* __restrict__ pnw, const float* __restrict__ pnb,
                              const float* __restrict__ bw, const float* __restrict__ bb) {
    __shared__ float zc[64][68];
    __shared__ float sbw[16][68];
    __shared__ float spnw[64], spnb[64];
    int tid = threadIdx.x;                 // 256
    int h = blockIdx.x >> 10;
    int x = blockIdx.x & 1023;
    int i = h * 64 + (x >> 4);
    int n = x & 15;
    const float* src = z + (size_t)(i * 1024 + n * 64) * 64;
#pragma unroll
    for (int t = 0; t < 4; t++) {
        int f4 = tid + t * 256;            // float4 index 0..1023
        float4 v = *(const float4*)(src + f4 * 4);
        int flat = f4 * 4;
        *(float4*)&zc[flat >> 6][flat & 63] = v;
    }
    {
        int flat = tid * 4;                // 1024 floats of bias_w
        *(float4*)&sbw[flat >> 6][flat & 63] = *(const float4*)(bw + flat);
    }
    if (tid < 64) { spnw[tid] = pnw[tid]; spnb[tid] = pnb[tid]; }
    __syncthreads();

    int jj = tid >> 2;                     // 0..63 (j within 64-run)
    int t4 = tid & 3;                      // lane in group of 4
    float su = 0.f, sq = 0.f;
#pragma unroll
    for (int q = 0; q < 16; q++) {
        float vz = zc[jj][t4 + q * 4];
        su += vz; sq += vz * vz;
    }
    su += __shfl_xor_sync(0xffffffffu, su, 1); su += __shfl_xor_sync(0xffffffffu, su, 2);
    sq += __shfl_xor_sync(0xffffffffu, sq, 1); sq += __shfl_xor_sync(0xffffffffu, sq, 2);
    float m = su * (1.f / 64.f);
    float rs = rsqrtf(sq * (1.f / 64.f) - m * m + EPSV);

    float o0 = bb[t4 * 4 + 0], o1 = bb[t4 * 4 + 1], o2 = bb[t4 * 4 + 2], o3 = bb[t4 * 4 + 3];
#pragma unroll
    for (int cc = 0; cc < 64; cc++) {
        float zn = (zc[jj][cc] - m) * rs * spnw[cc] + spnb[cc];
        o0 += zn * sbw[t4 * 4 + 0][cc];
        o1 += zn * sbw[t4 * 4 + 1][cc];
        o2 += zn * sbw[t4 * 4 + 2][cc];
        o3 += zn * sbw[t4 * 4 + 3][cc];
    }
    float4 outv = {o0, o1, o2, o3};
    *(float4*)(g_bias + ((size_t)h * S + x) * S + jj * 16 + t4 * 4) = outv;
}

// ---------------- 7. scores[h][x][y] += (K[h,x,:]·Q[h,y,:]) / 64  (in place on bias) ----------------
__global__ void scores_kernel() {
    int h = blockIdx.z;
    const float* Kh = g_K + (h << 16);
    const float* Qh = g_Q + (h << 16);
    __shared__ float As[16][68], Bs[16][68];
    int tid = threadIdx.x;
    int m0 = blockIdx.y * 64, n0 = blockIdx.x * 64;
    int lr = tid >> 2, lc = (tid & 3) * 4;
    int ty = tid >> 4, tx = tid & 15;
    float acc[4][4] = {};
    for (int kt = 0; kt < 64; kt += 16) {
        stsT(As, lc, lr, *(const float4*)(Kh + (m0 + lr) * 64 + kt + lc));
        stsT(Bs, lc, lr, *(const float4*)(Qh + (n0 + lr) * 64 + kt + lc));
        __syncthreads();
#pragma unroll
        for (int k = 0; k < 16; k++)
            fma44(acc, *(const float4*)&As[k][ty * 4], *(const float4*)&Bs[k][tx * 4]);
        __syncthreads();
    }
#pragma unroll
    for (int i = 0; i < 4; i++) {
        int x = m0 + ty * 4 + i;
        float* bp = g_bias + ((size_t)h * S + x) * S + n0 + tx * 4;
        float4 b = *(float4*)bp;
        b.x += acc[i][0] * (1.f / 64.f);
        b.y += acc[i][1] * (1.f / 64.f);
        b.z += acc[i][2] * (1.f / 64.f);
        b.w += acc[i][3] * (1.f / 64.f);
        *(float4*)bp = b;
    }
}

// ---------------- 8. softmax over y, in place (16384 rows x 1024) ----------------
__global__ void softmax_kernel() {
    __shared__ float sm[8];
    float* rowp = g_bias + (size_t)blockIdx.x * S;
    int tid = threadIdx.x;
    float4 v = *(float4*)(rowp + tid * 4);
    float mx = fmaxf(fmaxf(v.x, v.y), fmaxf(v.z, v.w));
    mx = warp_max(mx);
    if ((tid & 31) == 0) sm[tid >> 5] = mx;
    __syncthreads();
    float tm = sm[0];
#pragma unroll
    for (int i = 1; i < 8; i++) tm = fmaxf(tm, sm[i]);
    v.x = __expf(v.x - tm); v.y = __expf(v.y - tm);
    v.z = __expf(v.z - tm); v.w = __expf(v.w - tm);
    float su = v.x + v.y + v.z + v.w;
    su = warp_sum(su);
    __syncthreads();
    if ((tid & 31) == 0) sm[tid >> 5] = su;
    __syncthreads();
    float ts = 0.f;
#pragma unroll
    for (int i = 0; i < 8; i++) ts += sm[i];
    float inv = 1.f / ts;
    v.x *= inv; v.y *= inv; v.z *= inv; v.w *= inv;
    *(float4*)(rowp + tid * 4) = v;
}

// ---------------- 9. o[h][j][c] = sum_x A[h][x][j] * V[h][x][c];  GO = g*o scattered ----------------
__global__ void o_gemm_kernel() {
    int h = blockIdx.z;
    const float* Ah = g_bias + ((size_t)h << 20);
    const float* Vh = g_V + (h << 16);
    const float* Gh = g_G + (h << 16);
    __shared__ float As[16][68], Bs[16][68];
    int tid = threadIdx.x;
    int m0 = blockIdx.y * 64;              // j tile; c covers all 64
    int lr = tid >> 4, lc = (tid & 15) * 4;
    int ty = tid >> 4, tx = tid & 15;
    float acc[4][4] = {};
    for (int kt = 0; kt < S; kt += 16) {
        *(float4*)&As[lr][lc] = *(const float4*)(Ah + (size_t)(kt + lr) * S + m0 + lc);
        *(float4*)&Bs[lr][lc] = *(const float4*)(Vh + (kt + lr) * 64 + lc);
        __syncthreads();
#pragma unroll
        for (int k = 0; k < 16; k++)
            fma44(acc, *(const float4*)&As[k][ty * 4], *(const float4*)&Bs[k][tx * 4]);
        __syncthreads();
    }
#pragma unroll
    for (int i = 0; i < 4; i++) {
        int j = m0 + ty * 4 + i;
        float4 gv = *(const float4*)(Gh + j * 64 + tx * 4);
        float4 r = {acc[i][0] * gv.x, acc[i][1] * gv.y, acc[i][2] * gv.z, acc[i][3] * gv.w};
        *(float4*)(g_GO + (h * 64 + (j >> 4)) * CA + ((j & 15) << 6) + tx * 4) = r;
    }
}

// ---------------- 10. out = sigmoid(s@out_w^T + out_b) * (GO@attn_w^T) ----------------
__global__ void final_gemm_kernel(const float* __restrict__ aw, const float* __restrict__ sIn,
                                  const float* __restrict__ ow, const float* __restrict__ ob,
                                  float* __restrict__ outp) {
    __shared__ float As[16][68], Bs[16][68], Cs[16][68], Ds[16][68];
    int tid = threadIdx.x;
    int m0 = blockIdx.y * 64, n0 = blockIdx.x * 64;
    int lr = tid >> 2, lc = (tid & 3) * 4;
    int ty = tid >> 4, tx = tid & 15;
    float acc1[4][4] = {}, acc2[4][4] = {};
    for (int kt = 0; kt < CS; kt += 16) {
        stsT(As, lc, lr, *(const float4*)(g_GO + (m0 + lr) * CA + kt + lc));
        stsT(Bs, lc, lr, *(const float4*)(aw   + (n0 + lr) * CA + kt + lc));
        stsT(Cs, lc, lr, *(const float4*)(sIn  + (m0 + lr) * CS + kt + lc));
        stsT(Ds, lc, lr, *(const float4*)(ow   + (n0 + lr) * CS + kt + lc));
        __syncthreads();
#pragma unroll
        for (int k = 0; k < 16; k++) {
            fma44(acc1, *(const float4*)&As[k][ty * 4], *(const float4*)&Bs[k][tx * 4]);
            fma44(acc2, *(const float4*)&Cs[k][ty * 4], *(const float4*)&Ds[k][tx * 4]);
        }
        __syncthreads();
    }
    for (int kt = CS; kt < CA; kt += 16) {
        stsT(As, lc, lr, *(const float4*)(g_GO + (m0 + lr) * CA + kt + lc));
        stsT(Bs, lc, lr, *(const float4*)(aw   + (n0 + lr) * CA + kt + lc));
        __syncthreads();
#pragma unroll
        for (int k = 0; k < 16; k++)
            fma44(acc1, *(const float4*)&As[k][ty * 4], *(const float4*)&Bs[k][tx * 4]);
        __syncthreads();
    }
    float4 obv = *(const float4*)(ob + n0 + tx * 4);
    float obb[4] = {obv.x, obv.y, obv.z, obv.w};
#pragma unroll
    for (int i = 0; i < 4; i++) {
        int row = m0 + ty * 4 + i;
        float4 r;
        r.x = acc1[i][0] * sigm(acc2[i][0] + obb[0]);
        r.y = acc1[i][1] * sigm(acc2[i][1] + obb[1]);
        r.z = acc1[i][2] * sigm(acc2[i][2] + obb[2]);
        r.w = acc1[i][3] * sigm(acc2[i][3] + obb[3]);
        *(float4*)(outp + row * CA + n0 + tx * 4) = r;
    }
}

// ---------------- launch ----------------
extern "C" void kernel_launch(void* const* d_in, const int* in_sizes, int n_in,
                              void* d_out, int out_size) {
    (void)in_sizes; (void)n_in; (void)out_size;
    const float* a       = (const float*)d_in[0];
    const float* z       = (const float*)d_in[1];
    const float* s       = (const float*)d_in[2];
    const float* sn_w    = (const float*)d_in[3];
    const float* pb_w    = (const float*)d_in[4];
    const float* pb_b    = (const float*)d_in[5];
    const float* pn_w    = (const float*)d_in[6];
    const float* pnorm_w = (const float*)d_in[7];
    const float* pnorm_b = (const float*)d_in[8];
    const float* q_w     = (const float*)d_in[9];
    const float* q_b     = (const float*)d_in[10];
    const float* kvg_w   = (const float*)d_in[11];
    const float* bias_w  = (const float*)d_in[12];
    const float* bias_b  = (const float*)d_in[13];
    const float* attn_w  = (const float*)d_in[14];
    const float* out_w   = (const float*)d_in[15];
    const float* out_b   = (const float*)d_in[16];
    float* out = (float*)d_out;

    ln_s_kernel<<<S, 256>>>(s, sn_w);
    ln_a_kernel<<<S, 256>>>(a);
    adaln_gemm_kernel<<<dim3(16, 16), 256>>>(pb_w, pb_b, pn_w);
    q_gemm_kernel<<<dim3(16, 16), 256>>>(q_w, q_b);
    kvg_gemm_kernel<<<dim3(48, 16), 256>>>(kvg_w);
    bias_z_kernel<<<NH * S, 256>>>(z, pnorm_w, pnorm_b, bias_w, bias_b);
    scores_kernel<<<dim3(16, 16, NH), 256>>>();
    softmax_kernel<<<NH * S, 256>>>();
    o_gemm_kernel<<<dim3(1, 16, NH), 256>>>();
    final_gemm_kernel<<<dim3(16, 16), 256>>>(attn_w, s, out_w, out_b, out);
}

// round 4
// speedup vs baseline: 1.3127x; 1.3127x over previous
#include <cuda_runtime.h>
#include <cstdint>
#include <math.h>

// AttentionPairBias: B=1, S=1024, ca=1024, cs=512, cz=64, H=16, c=64
#define S    1024
#define CA   1024
#define CS   512
#define NH   16
#define EPSV 1e-5f

// ---------------- scratch ----------------
__device__ float g_sn[S * CS];
__device__ float g_an[S * CA];
__device__ float g_a1[S * CA];
__device__ float g_Q[NH * S * 64];
__device__ float g_K[NH * S * 64];
__device__ float g_V[NH * S * 64];
__device__ float g_G[NH * S * 64];
__device__ float g_bias[(size_t)NH * S * S];
__device__ float g_GO[S * CA];

// ---------------- helpers ----------------
__device__ __forceinline__ float warp_sum(float v) {
#pragma unroll
    for (int o = 16; o; o >>= 1) v += __shfl_xor_sync(0xffffffffu, v, o);
    return v;
}
__device__ __forceinline__ float warp_max(float v) {
#pragma unroll
    for (int o = 16; o; o >>= 1) v = fmaxf(v, __shfl_xor_sync(0xffffffffu, v, o));
    return v;
}
__device__ __forceinline__ float sigm(float x) { return 1.f / (1.f + __expf(-x)); }

__device__ __forceinline__ uint32_t f2tf(float f) {
    uint32_t u; asm("cvt.rna.tf32.f32 %0, %1;" : "=r"(u) : "f"(f)); return u;
}
__device__ __forceinline__ void mma8(float* d, const uint32_t* a, const uint32_t* b) {
    asm volatile(
        "mma.sync.aligned.m16n8k8.row.col.f32.tf32.tf32.f32 "
        "{%0,%1,%2,%3},{%4,%5,%6,%7},{%8,%9},{%0,%1,%2,%3};\n"
        : "+f"(d[0]), "+f"(d[1]), "+f"(d[2]), "+f"(d[3])
        : "r"(a[0]), "r"(a[1]), "r"(a[2]), "r"(a[3]), "r"(b[0]), "r"(b[1]));
}

// load ROWS x 16 tile from row-major (k-contig) src, store TRANSPOSED [k][row] as tf32
template<int ROWS, int TS>
__device__ __forceinline__ void ldT(uint32_t* T, const float* src, int ld, int tid) {
#pragma unroll
    for (int t = 0; t < ROWS / 64; t++) {
        int idx = tid + t * 256;
        int r = idx >> 2;
        int kq = (idx & 3) << 2;
        float4 v = *(const float4*)(src + (size_t)r * ld + kq);
        T[(kq + 0) * TS + r] = f2tf(v.x);
        T[(kq + 1) * TS + r] = f2tf(v.y);
        T[(kq + 2) * TS + r] = f2tf(v.z);
        T[(kq + 3) * TS + r] = f2tf(v.w);
    }
}
// load 16 x COLS tile from k-major src directly as [k][col]
template<int COLS, int TS>
__device__ __forceinline__ void ldD(uint32_t* T, const float* src, size_t ld, int tid) {
    constexpr int C4 = COLS / 4;
#pragma unroll
    for (int t = 0; t < (16 * C4) / 256; t++) {
        int idx = tid + t * 256;
        int kr = idx / C4;
        int c4 = (idx % C4) * 4;
        float4 v = *(const float4*)(src + (size_t)kr * ld + c4);
        uint32_t* p = T + kr * TS + c4;
        p[0] = f2tf(v.x); p[1] = f2tf(v.y); p[2] = f2tf(v.z); p[3] = f2tf(v.w);
    }
}

// warp compute over one 16-deep k-tile: warp tile 32x32 (MT=2 m-tiles, NT=4 n-tiles)
template<int TSA, int TSB>
__device__ __forceinline__ void kblock(float (&acc)[2][4][4], const uint32_t* As,
                                       const uint32_t* Bs, int mw, int nw, int lane) {
    int r0 = lane >> 2, k0 = lane & 3, nn = lane >> 2;
#pragma unroll
    for (int ks = 0; ks < 2; ks++) {
        uint32_t a[2][4], b[4][2];
#pragma unroll
        for (int mt = 0; mt < 2; mt++) {
            const uint32_t* p = As + (ks * 8 + k0) * TSA + mw + mt * 16 + r0;
            a[mt][0] = p[0]; a[mt][1] = p[8];
            a[mt][2] = p[4 * TSA]; a[mt][3] = p[4 * TSA + 8];
        }
#pragma unroll
        for (int nt = 0; nt < 4; nt++) {
            const uint32_t* p = Bs + (ks * 8 + k0) * TSB + nw + nt * 8 + nn;
            b[nt][0] = p[0]; b[nt][1] = p[4 * TSB];
        }
#pragma unroll
        for (int mt = 0; mt < 2; mt++)
#pragma unroll
            for (int nt = 0; nt < 4; nt++) mma8(acc[mt][nt], a[mt], b[nt]);
    }
}

#define TILE_SETUP                                    \
    int tid = threadIdx.x, lane = tid & 31;           \
    int wid = tid >> 5;                               \
    int mw = (wid >> 1) * 32, nw = (wid & 1) * 32;    \
    int r0 = lane >> 2, c2 = (lane & 3) * 2;

// ---------------- 1/2. layernorms (unchanged) ----------------
__global__ void ln_s_kernel(const float* __restrict__ s, const float* __restrict__ snw) {
    __shared__ float sm[16];
    int row = blockIdx.x, tid = threadIdx.x;
    const float* x = s + row * CS;
    float2 v = *(const float2*)(x + tid * 2);
    float su = v.x + v.y, sq = v.x * v.x + v.y * v.y;
    su = warp_sum(su); sq = warp_sum(sq);
    if ((tid & 31) == 0) { sm[tid >> 5] = su; sm[8 + (tid >> 5)] = sq; }
    __syncthreads();
    float ts = 0.f, tq = 0.f;
#pragma unroll
    for (int i = 0; i < 8; i++) { ts += sm[i]; tq += sm[8 + i]; }
    float m = ts * (1.f / CS);
    float rs = rsqrtf(tq * (1.f / CS) - m * m + EPSV);
    float2 w = *(const float2*)(snw + tid * 2);
    float2 r; r.x = (v.x - m) * rs * w.x; r.y = (v.y - m) * rs * w.y;
    *(float2*)(g_sn + row * CS + tid * 2) = r;
}
__global__ void ln_a_kernel(const float* __restrict__ a) {
    __shared__ float sm[16];
    int row = blockIdx.x, tid = threadIdx.x;
    const float* x = a + row * CA;
    float4 v = *(const float4*)(x + tid * 4);
    float su = v.x + v.y + v.z + v.w;
    float sq = v.x * v.x + v.y * v.y + v.z * v.z + v.w * v.w;
    su = warp_sum(su); sq = warp_sum(sq);
    if ((tid & 31) == 0) { sm[tid >> 5] = su; sm[8 + (tid >> 5)] = sq; }
    __syncthreads();
    float ts = 0.f, tq = 0.f;
#pragma unroll
    for (int i = 0; i < 8; i++) { ts += sm[i]; tq += sm[8 + i]; }
    float m = ts * (1.f / CA);
    float rs = rsqrtf(tq * (1.f / CA) - m * m + EPSV);
    float4 r;
    r.x = (v.x - m) * rs; r.y = (v.y - m) * rs;
    r.z = (v.z - m) * rs; r.w = (v.w - m) * rs;
    *(float4*)(g_an + row * CA + tid * 4) = r;
}

// ---------------- 3. adaLN dual GEMM (tf32 mma), M=1024 N=1024 K=512 ----------------
__global__ void adaln_tc(const float* __restrict__ pbw, const float* __restrict__ pbb,
                         const float* __restrict__ pnw) {
    __shared__ uint32_t As[16][136], B1s[16][72], B2s[16][72];
    TILE_SETUP
    int m0 = blockIdx.y * 128, n0 = blockIdx.x * 64;
    float acc1[2][4][4] = {}, acc2[2][4][4] = {};
    for (int kt = 0; kt < CS; kt += 16) {
        ldT<128, 136>(&As[0][0], g_sn + (size_t)m0 * CS + kt, CS, tid);
        ldT<64, 72>(&B1s[0][0], pbw + (size_t)n0 * CS + kt, CS, tid);
        ldT<64, 72>(&B2s[0][0], pnw + (size_t)n0 * CS + kt, CS, tid);
        __syncthreads();
        kblock<136, 72>(acc1, &As[0][0], &B1s[0][0], mw, nw, lane);
        kblock<136, 72>(acc2, &As[0][0], &B2s[0][0], mw, nw, lane);
        __syncthreads();
    }
#pragma unroll
    for (int mt = 0; mt < 2; mt++)
#pragma unroll
        for (int nt = 0; nt < 4; nt++) {
            int col = n0 + nw + nt * 8 + c2;
            float2 bb = *(const float2*)(pbb + col);
#pragma unroll
            for (int hf = 0; hf < 2; hf++) {
                int row = m0 + mw + mt * 16 + r0 + hf * 8;
                float2 an = *(const float2*)(g_an + (size_t)row * CA + col);
                float2 r;
                r.x = sigm((acc1[mt][nt][hf * 2 + 0] + bb.x) * an.x + acc2[mt][nt][hf * 2 + 0]);
                r.y = sigm((acc1[mt][nt][hf * 2 + 1] + bb.y) * an.y + acc2[mt][nt][hf * 2 + 1]);
                *(float2*)(g_a1 + (size_t)row * CA + col) = r;
            }
        }
}

// ---------------- 4. Q projection (tf32), scatter to [h][y][c] ----------------
__global__ void q_tc(const float* __restrict__ qw, const float* __restrict__ qb) {
    __shared__ uint32_t As[16][136], Bs[16][72];
    TILE_SETUP
    int m0 = blockIdx.y * 128, n0 = blockIdx.x * 64;
    float acc[2][4][4] = {};
    for (int kt = 0; kt < CA; kt += 16) {
        ldT<128, 136>(&As[0][0], g_a1 + (size_t)m0 * CA + kt, CA, tid);
        ldT<64, 72>(&Bs[0][0], qw + (size_t)n0 * CA + kt, CA, tid);
        __syncthreads();
        kblock<136, 72>(acc, &As[0][0], &Bs[0][0], mw, nw, lane);
        __syncthreads();
    }
#pragma unroll
    for (int mt = 0; mt < 2; mt++)
#pragma unroll
        for (int nt = 0; nt < 4; nt++) {
            int col = n0 + nw + nt * 8 + c2;
            float2 bb = *(const float2*)(qb + col);
#pragma unroll
            for (int hf = 0; hf < 2; hf++) {
                int row = m0 + mw + mt * 16 + r0 + hf * 8;
                int h = row >> 6;
                int y = ((row & 63) << 4) + (col >> 6);
                int cc = col & 63;
                float2 r = {acc[mt][nt][hf * 2] + bb.x, acc[mt][nt][hf * 2 + 1] + bb.y};
                *(float2*)(g_Q + (h << 16) + y * 64 + cc) = r;
            }
        }
}

// ---------------- 5. KVG projection (tf32), scatter to K/V/sigmoid(G) ----------------
__global__ void kvg_tc(const float* __restrict__ kvgw) {
    __shared__ uint32_t As[16][136], Bs[16][72];
    TILE_SETUP
    int m0 = blockIdx.y * 128, n0 = blockIdx.x * 64;
    float acc[2][4][4] = {};
    for (int kt = 0; kt < CA; kt += 16) {
        ldT<128, 136>(&As[0][0], g_a1 + (size_t)m0 * CA + kt, CA, tid);
        ldT<64, 72>(&Bs[0][0], kvgw + (size_t)n0 * CA + kt, CA, tid);
        __syncthreads();
        kblock<136, 72>(acc, &As[0][0], &Bs[0][0], mw, nw, lane);
        __syncthreads();
    }
#pragma unroll
    for (int mt = 0; mt < 2; mt++)
#pragma unroll
        for (int nt = 0; nt < 4; nt++) {
            int col = n0 + nw + nt * 8 + c2;
#pragma unroll
            for (int hf = 0; hf < 2; hf++) {
                int row = m0 + mw + mt * 16 + r0 + hf * 8;
                int h = row >> 6;
                int y = ((row & 63) << 4) + col / 192;
                int t0 = col % 192;
                int which = t0 >> 6;
                int cc = t0 & 63;
                float2 r = {acc[mt][nt][hf * 2], acc[mt][nt][hf * 2 + 1]};
                int off = (h << 16) + y * 64 + cc;
                if (which == 0) *(float2*)(g_K + off) = r;
                else if (which == 1) *(float2*)(g_V + off) = r;
                else { float2 rg = {sigm(r.x), sigm(r.y)}; *(float2*)(g_G + off) = rg; }
            }
        }
}

// ---------------- 6. bias[h][x][y] from z (unchanged) ----------------
__global__ void bias_z_kernel(const float* __restrict__ z,
                              const float* __restrict__ pnw, const float* __restrict__ pnb,
                              const float* __restrict__ bw, const float* __restrict__ bb) {
    __shared__ float zc[64][68];
    __shared__ float sbw[16][68];
    __shared__ float spnw[64], spnb[64];
    int tid = threadIdx.x;
    int h = blockIdx.x >> 10;
    int x = blockIdx.x & 1023;
    int i = h * 64 + (x >> 4);
    int n = x & 15;
    const float* src = z + (size_t)(i * 1024 + n * 64) * 64;
#pragma unroll
    for (int t = 0; t < 4; t++) {
        int f4 = tid + t * 256;
        float4 v = *(const float4*)(src + f4 * 4);
        int flat = f4 * 4;
        *(float4*)&zc[flat >> 6][flat & 63] = v;
    }
    {
        int flat = tid * 4;
        *(float4*)&sbw[flat >> 6][flat & 63] = *(const float4*)(bw + flat);
    }
    if (tid < 64) { spnw[tid] = pnw[tid]; spnb[tid] = pnb[tid]; }
    __syncthreads();

    int jj = tid >> 2;
    int t4 = tid & 3;
    float su = 0.f, sq = 0.f;
#pragma unroll
    for (int q = 0; q < 16; q++) {
        float vz = zc[jj][t4 + q * 4];
        su += vz; sq += vz * vz;
    }
    su += __shfl_xor_sync(0xffffffffu, su, 1); su += __shfl_xor_sync(0xffffffffu, su, 2);
    sq += __shfl_xor_sync(0xffffffffu, sq, 1); sq += __shfl_xor_sync(0xffffffffu, sq, 2);
    float m = su * (1.f / 64.f);
    float rs = rsqrtf(sq * (1.f / 64.f) - m * m + EPSV);

    float o0 = bb[t4 * 4 + 0], o1 = bb[t4 * 4 + 1], o2 = bb[t4 * 4 + 2], o3 = bb[t4 * 4 + 3];
#pragma unroll
    for (int cc = 0; cc < 64; cc++) {
        float zn = (zc[jj][cc] - m) * rs * spnw[cc] + spnb[cc];
        o0 += zn * sbw[t4 * 4 + 0][cc];
        o1 += zn * sbw[t4 * 4 + 1][cc];
        o2 += zn * sbw[t4 * 4 + 2][cc];
        o3 += zn * sbw[t4 * 4 + 3][cc];
    }
    float4 outv = {o0, o1, o2, o3};
    *(float4*)(g_bias + ((size_t)h * S + x) * S + jj * 16 + t4 * 4) = outv;
}

// ---------------- 7. scores += K·Q^T / 64  (tf32, in-place RMW on bias) ----------------
__global__ void scores_tc() {
    __shared__ uint32_t As[16][136], Bs[16][72];
    TILE_SETUP
    int h = blockIdx.z;
    int m0 = blockIdx.y * 128, n0 = blockIdx.x * 64;
    const float* Kh = g_K + (h << 16);
    const float* Qh = g_Q + (h << 16);
    float acc[2][4][4] = {};
    for (int kt = 0; kt < 64; kt += 16) {
        ldT<128, 136>(&As[0][0], Kh + (size_t)m0 * 64 + kt, 64, tid);
        ldT<64, 72>(&Bs[0][0], Qh + (size_t)n0 * 64 + kt, 64, tid);
        __syncthreads();
        kblock<136, 72>(acc, &As[0][0], &Bs[0][0], mw, nw, lane);
        __syncthreads();
    }
#pragma unroll
    for (int mt = 0; mt < 2; mt++)
#pragma unroll
        for (int nt = 0; nt < 4; nt++) {
            int col = n0 + nw + nt * 8 + c2;
#pragma unroll
            for (int hf = 0; hf < 2; hf++) {
                int row = m0 + mw + mt * 16 + r0 + hf * 8;
                float* bp = g_bias + ((size_t)h * S + row) * S + col;
                float2 b = *(float2*)bp;
                b.x += acc[mt][nt][hf * 2] * (1.f / 64.f);
                b.y += acc[mt][nt][hf * 2 + 1] * (1.f / 64.f);
                *(float2*)bp = b;
            }
        }
}

// ---------------- 8. softmax over y, in place (unchanged) ----------------
__global__ void softmax_kernel() {
    __shared__ float sm[8];
    float* rowp = g_bias + (size_t)blockIdx.x * S;
    int tid = threadIdx.x;
    float4 v = *(float4*)(rowp + tid * 4);
    float mx = fmaxf(fmaxf(v.x, v.y), fmaxf(v.z, v.w));
    mx = warp_max(mx);
    if ((tid & 31) == 0) sm[tid >> 5] = mx;
    __syncthreads();
    float tm = sm[0];
#pragma unroll
    for (int i = 1; i < 8; i++) tm = fmaxf(tm, sm[i]);
    v.x = __expf(v.x - tm); v.y = __expf(v.y - tm);
    v.z = __expf(v.z - tm); v.w = __expf(v.w - tm);
    float su = v.x + v.y + v.z + v.w;
    su = warp_sum(su);
    __syncthreads();
    if ((tid & 31) == 0) sm[tid >> 5] = su;
    __syncthreads();
    float ts = 0.f;
#pragma unroll
    for (int i = 0; i < 8; i++) ts += sm[i];
    float inv = 1.f / ts;
    v.x *= inv; v.y *= inv; v.z *= inv; v.w *= inv;
    *(float4*)(rowp + tid * 4) = v;
}

// ---------------- 9. o = A^T V (tf32); GO = g*o scattered ----------------
__global__ void o_tc() {
    __shared__ uint32_t As[16][136], Bs[16][72];
    TILE_SETUP
    int h = blockIdx.y;
    int m0 = blockIdx.x * 128;   // j tile; c covers all 64 (n0 = 0)
    const float* Ah = g_bias + ((size_t)h << 20);
    const float* Vh = g_V + (h << 16);
    const float* Gh = g_G + (h << 16);
    float acc[2][4][4] = {};
    for (int kt = 0; kt < S; kt += 16) {
        ldD<128, 136>(&As[0][0], Ah + (size_t)kt * S + m0, S, tid);
        ldD<64, 72>(&Bs[0][0], Vh + (size_t)kt * 64, 64, tid);
        __syncthreads();
        kblock<136, 72>(acc, &As[0][0], &Bs[0][0], mw, nw, lane);
        __syncthreads();
    }
#pragma unroll
    for (int mt = 0; mt < 2; mt++)
#pragma unroll
        for (int nt = 0; nt < 4; nt++) {
            int col = nw + nt * 8 + c2;
#pragma unroll
            for (int hf = 0; hf < 2; hf++) {
                int j = m0 + mw + mt * 16 + r0 + hf * 8;
                float2 g = *(const float2*)(Gh + j * 64 + col);
                float2 r = {acc[mt][nt][hf * 2] * g.x, acc[mt][nt][hf * 2 + 1] * g.y};
                *(float2*)(g_GO + (h * 64 + (j >> 4)) * CA + ((j & 15) << 6) + col) = r;
            }
        }
}

// ---------------- 10. final dual GEMM: out = sigmoid(s@ow^T+ob) * (GO@aw^T) ----------------
__global__ void final_tc(const float* __restrict__ aw, const float* __restrict__ sIn,
                         const float* __restrict__ ow, const float* __restrict__ ob,
                         float* __restrict__ outp) {
    __shared__ uint32_t As[16][136], Cs[16][136], Bs[16][72], Ds[16][72];
    TILE_SETUP
    int m0 = blockIdx.y * 128, n0 = blockIdx.x * 64;
    float acc1[2][4][4] = {}, acc2[2][4][4] = {};
    for (int kt = 0; kt < CS; kt += 16) {
        ldT<128, 136>(&As[0][0], g_GO + (size_t)m0 * CA + kt, CA, tid);
        ldT<64, 72>(&Bs[0][0], aw + (size_t)n0 * CA + kt, CA, tid);
        ldT<128, 136>(&Cs[0][0], sIn + (size_t)m0 * CS + kt, CS, tid);
        ldT<64, 72>(&Ds[0][0], ow + (size_t)n0 * CS + kt, CS, tid);
        __syncthreads();
        kblock<136, 72>(acc1, &As[0][0], &Bs[0][0], mw, nw, lane);
        kblock<136, 72>(acc2, &Cs[0][0], &Ds[0][0], mw, nw, lane);
        __syncthreads();
    }
    for (int kt = CS; kt < CA; kt += 16) {
        ldT<128, 136>(&As[0][0], g_GO + (size_t)m0 * CA + kt, CA, tid);
        ldT<64, 72>(&Bs[0][0], aw + (size_t)n0 * CA + kt, CA, tid);
        __syncthreads();
        kblock<136, 72>(acc1, &As[0][0], &Bs[0][0], mw, nw, lane);
        __syncthreads();
    }
#pragma unroll
    for (int mt = 0; mt < 2; mt++)
#pragma unroll
        for (int nt = 0; nt < 4; nt++) {
            int col = n0 + nw + nt * 8 + c2;
            float2 obv = *(const float2*)(ob + col);
#pragma unroll
            for (int hf = 0; hf < 2; hf++) {
                int row = m0 + mw + mt * 16 + r0 + hf * 8;
                float2 r;
                r.x = acc1[mt][nt][hf * 2] * sigm(acc2[mt][nt][hf * 2] + obv.x);
                r.y = acc1[mt][nt][hf * 2 + 1] * sigm(acc2[mt][nt][hf * 2 + 1] + obv.y);
                *(float2*)(outp + (size_t)row * CA + col) = r;
            }
        }
}

// ---------------- launch ----------------
extern "C" void kernel_launch(void* const* d_in, const int* in_sizes, int n_in,
                              void* d_out, int out_size) {
    (void)in_sizes; (void)n_in; (void)out_size;
    const float* a       = (const float*)d_in[0];
    const float* z       = (const float*)d_in[1];
    const float* s       = (const float*)d_in[2];
    const float* sn_w    = (const float*)d_in[3];
    const float* pb_w    = (const float*)d_in[4];
    const float* pb_b    = (const float*)d_in[5];
    const float* pn_w    = (const float*)d_in[6];
    const float* pnorm_w = (const float*)d_in[7];
    const float* pnorm_b = (const float*)d_in[8];
    const float* q_w     = (const float*)d_in[9];
    const float* q_b     = (const float*)d_in[10];
    const float* kvg_w   = (const float*)d_in[11];
    const float* bias_w  = (const float*)d_in[12];
    const float* bias_b  = (const float*)d_in[13];
    const float* attn_w  = (const float*)d_in[14];
    const float* out_w   = (const float*)d_in[15];
    const float* out_b   = (const float*)d_in[16];
    float* out = (float*)d_out;

    ln_s_kernel<<<S, 256>>>(s, sn_w);
    ln_a_kernel<<<S, 256>>>(a);
    adaln_tc<<<dim3(16, 8), 256>>>(pb_w, pb_b, pn_w);
    q_tc<<<dim3(16, 8), 256>>>(q_w, q_b);
    kvg_tc<<<dim3(48, 8), 256>>>(kvg_w);
    bias_z_kernel<<<NH * S, 256>>>(z, pnorm_w, pnorm_b, bias_w, bias_b);
    scores_tc<<<dim3(16, 8, NH), 256>>>();
    softmax_kernel<<<NH * S, 256>>>();
    o_tc<<<dim3(8, NH), 256>>>();
    final_tc<<<dim3(16, 8), 256>>>(attn_w, s, out_w, out_b, out);
}